// round 14
// baseline (speedup 1.0000x reference)
#include <cuda_runtime.h>
#include <cuda_fp16.h>
#include <math.h>
#include <stdint.h>

// ================= persistent device scratch =================
__device__ __align__(16) __half g_Bk[10*3*128*1600];      // [s][kz][c(128)][kk*320+e] fp16 weights
__device__ __align__(16) __half g_Ah[10*256*48*320];      // [s][item][t][e(320)] fp16 news
__device__ float g_tfeat[10*256*300];
__device__ float g_xp[10*256*512];
__device__ float g_hn[10*16*128];
__device__ float g_hsum[10*16*128];
__device__ float g_text[16*640];

// ================= helpers =================
__device__ __forceinline__ uint32_t smem_u32(const void* p) {
    uint32_t a;
    asm("{ .reg .u64 t; cvta.to.shared.u64 t, %1; cvt.u32.u64 %0, t; }" : "=r"(a) : "l"(p));
    return a;
}

#define MMA_F16(c, a, b0, b1) \
    asm volatile("mma.sync.aligned.m16n8k16.row.col.f32.f16.f16.f32 " \
        "{%0,%1,%2,%3}, {%4,%5,%6,%7}, {%8,%9}, {%0,%1,%2,%3};" \
        : "+f"((c)[0]), "+f"((c)[1]), "+f"((c)[2]), "+f"((c)[3]) \
        : "r"((a)[0]), "r"((a)[1]), "r"((a)[2]), "r"((a)[3]), \
          "r"(b0), "r"(b1))

#define LDSM_X4(r0, r1, r2, r3, addr) \
    asm volatile("ldmatrix.sync.aligned.m8n8.x4.shared.b16 {%0,%1,%2,%3}, [%4];" \
        : "=r"(r0), "=r"(r1), "=r"(r2), "=r"(r3) : "r"(addr))

#define CP16(dst, src) \
    asm volatile("cp.async.cg.shared.global [%0], [%1], 16;" :: "r"(dst), "l"(src) : "memory")
#define CP16Z(dst, src, sz) \
    asm volatile("cp.async.cg.shared.global [%0], [%1], 16, %2;" :: "r"(dst), "l"(src), "r"(sz) : "memory")
#define CP_COMMIT() asm volatile("cp.async.commit_group;" ::: "memory")

// ================= merged prep: A (news->fp16 padded) + B (weights->fp16) ==========
__global__ void prep_kernel(const float* __restrict__ news,
                            const float* __restrict__ W3,
                            const float* __restrict__ W4,
                            const float* __restrict__ W5) {
    int idx = blockIdx.x * 256 + threadIdx.x;
    if (idx < 10*256*48*40) {
        // ---- A path ----
        int e8   = idx % 40;
        int t    = (idx / 40) % 48;
        int item = (idx / (40*48)) % 256;
        int s    = idx / (40*48*256);
        int e0 = e8 * 8;
        int bb = item >> 4, dd = item & 15;
        const float* src = news + ((size_t)((bb*10 + s)*16 + dd)*48 + t)*300 + e0;
        uint32_t pk[4];
        #pragma unroll
        for (int i = 0; i < 4; i++) {
            int e = e0 + i*2;
            float v0 = (e     < 300) ? src[i*2]     : 0.f;
            float v1 = (e + 1 < 300) ? src[i*2 + 1] : 0.f;
            __half2 h = __floats2half2_rn(v0, v1);
            pk[i] = *(uint32_t*)&h;
        }
        *(uint4*)(g_Ah + ((size_t)((s*256 + item)*48 + t))*320 + e0) =
            make_uint4(pk[0], pk[1], pk[2], pk[3]);
    } else {
        int jdx = idx - 10*256*48*40;
        if (jdx >= 10*3*128*200) return;
        int c40 = jdx % 40;
        int kk  = (jdx / 40) % 5;
        int c   = (jdx / 200) % 128;
        int kz  = (jdx / (200*128)) % 3;
        int s   = jdx / (200*128*3);
        int e0 = c40 * 8;
        int K  = 3 + kz;
        uint32_t pk[4];
        #pragma unroll
        for (int i = 0; i < 4; i++) {
            float v0 = 0.f, v1 = 0.f;
            int e = e0 + i*2;
            if (c < 100 && kk < K) {
                if (e < 300) {
                    if (kz == 0)      v0 = W3[((s*100+c)*300+e)*3 + kk];
                    else if (kz == 1) v0 = W4[((s*100+c)*300+e)*4 + kk];
                    else              v0 = W5[((s*100+c)*300+e)*5 + kk];
                }
                if (e + 1 < 300) {
                    if (kz == 0)      v1 = W3[((s*100+c)*300+e+1)*3 + kk];
                    else if (kz == 1) v1 = W4[((s*100+c)*300+e+1)*4 + kk];
                    else              v1 = W5[((s*100+c)*300+e+1)*5 + kk];
                }
            }
            __half2 h = __floats2half2_rn(v0, v1);
            pk[i] = *(uint32_t*)&h;
        }
        *(uint4*)(g_Bk + ((size_t)((s*3 + kz)*128 + c))*1600 + kk*320 + e0) =
            make_uint4(pk[0], pk[1], pk[2], pk[3]);
    }
}

// ================= fused conv GEMM: A resident in smem, B streamed (R11 config) =====
// grid (64, 3, 10). 512 threads / 16 warps: wm = wid&3 (item), wn = wid>>2 (32 cols).
// A smem: 4 items x 52 rows x 656 B = 136448 B (once). B ring: 3 x (128 x 176B).
__global__ void __launch_bounds__(512, 1)
conv_mma_kernel(const float* __restrict__ bc3,
                const float* __restrict__ bc4,
                const float* __restrict__ bc5) {
    extern __shared__ char smem[];
    uint32_t sb = smem_u32(smem);
    int tid = threadIdx.x, lane = tid & 31, wid = tid >> 5;
    int wm = wid & 3, wn = wid >> 2;
    int g = lane >> 2, tq = lane & 3;
    int mt = blockIdx.x, kz = blockIdx.y, s = blockIdx.z;
    int it0 = mt * 4;
    int S4 = 4 * (3 + kz);

    float acc[3][4][4];
    #pragma unroll
    for (int mf = 0; mf < 3; mf++)
        #pragma unroll
        for (int nf = 0; nf < 4; nf++)
            #pragma unroll
            for (int i = 0; i < 4; i++) acc[mf][nf][i] = 0.f;

    const __half* Bbase = g_Bk + (size_t)(s*3 + kz) * 128 * 1600;

    // ---- A resident load (once): 8528 chunks of 16B ----
    for (int c = tid; c < 8528; c += 512) {
        int row = c / 41, ch = c - row*41;
        int item = row / 52, tt = row - item*52;
        uint32_t sz = (tt < 48 && ch < 40) ? 16u : 0u;
        const __half* src = g_Ah +
            ((size_t)((s*256 + it0 + item)*48 + (tt < 48 ? tt : 47)))*320 + (ch < 40 ? ch : 0)*8;
        CP16Z(sb + (uint32_t)(row*656 + ch*16), src, sz);
    }
    CP_COMMIT();

    // ---- B loader precompute: 1280 chunks, 2.5/thread ----
    const __half* bsrc0; const __half* bsrc1; const __half* bsrc2 = 0;
    uint32_t bdst0, bdst1, bdst2 = 0;
    {
        int c = tid;           int n = c/10, ch = c - n*10;
        bsrc0 = Bbase + n*1600 + ch*8;  bdst0 = (uint32_t)(n*176 + ch*16);
        c = tid + 512;         n = c/10; ch = c - n*10;
        bsrc1 = Bbase + n*1600 + ch*8;  bdst1 = (uint32_t)(n*176 + ch*16);
        if (tid < 256) {
            c = tid + 1024;    n = c/10; ch = c - n*10;
            bsrc2 = Bbase + n*1600 + ch*8;  bdst2 = (uint32_t)(n*176 + ch*16);
        }
    }
    auto loadB = [&](int buf, int stoff) {
        uint32_t base = sb + 136448u + (uint32_t)buf * 22528u;
        CP16(base + bdst0, bsrc0 + stoff);
        CP16(base + bdst1, bsrc1 + stoff);
        if (tid < 256) CP16(base + bdst2, bsrc2 + stoff);
    };

    // ---- fragment ldmatrix base offsets ----
    uint32_t a_lm[3], b_lm[2];
    {
        int l15 = lane & 15;
        int hi  = (lane >> 4) & 1;
        #pragma unroll
        for (int mf = 0; mf < 3; mf++)
            a_lm[mf] = (uint32_t)((wm*52 + mf*16 + l15)*656 + hi*16);
        int l7 = lane & 7;
        int k8 = (lane >> 3) & 1;
        #pragma unroll
        for (int p = 0; p < 2; p++)
            b_lm[p] = (uint32_t)((wn*32 + p*16 + l7 + hi*8)*176 + k8*16);
    }

    loadB(0, 0);  CP_COMMIT();
    loadB(1, 80); CP_COMMIT();
    int nk = 0, ne = 160;

    int buf = 0;
    for (int st = 0; st < S4; st++) {
        if (st + 2 < S4) {
            asm volatile("cp.async.wait_group 1;" ::: "memory");
        } else {
            asm volatile("cp.async.wait_group 0;" ::: "memory");
        }
        __syncthreads();
        if (st + 2 < S4) {
            int nb = buf + 2; if (nb >= 3) nb -= 3;
            loadB(nb, nk*320 + ne);
            ne += 80; if (ne == 320) { ne = 0; nk++; }
            CP_COMMIT();
        }

        uint32_t aoff = sb + (uint32_t)(st >> 2)*656u + (uint32_t)(st & 3)*160u;
        uint32_t bbuf = sb + 136448u + (uint32_t)buf * 22528u;
        #pragma unroll
        for (int ks = 0; ks < 5; ks++) {
            uint32_t af[3][4];
            #pragma unroll
            for (int mf = 0; mf < 3; mf++)
                LDSM_X4(af[mf][0], af[mf][1], af[mf][2], af[mf][3],
                        aoff + a_lm[mf] + ks*32);
            uint32_t b0r[4], b1r[4];
            LDSM_X4(b0r[0], b0r[1], b0r[2], b0r[3], bbuf + b_lm[0] + ks*32);
            LDSM_X4(b1r[0], b1r[1], b1r[2], b1r[3], bbuf + b_lm[1] + ks*32);
            #pragma unroll
            for (int mf = 0; mf < 3; mf++) {
                MMA_F16(acc[mf][0], af[mf], b0r[0], b0r[1]);
                MMA_F16(acc[mf][1], af[mf], b0r[2], b0r[3]);
                MMA_F16(acc[mf][2], af[mf], b1r[0], b1r[1]);
                MMA_F16(acc[mf][3], af[mf], b1r[2], b1r[3]);
            }
        }
        buf++; if (buf == 3) buf = 0;
    }

    // ---- fused maxpool + bias epilogue ----
    int item = it0 + wm;
    int T = 46 - kz;
    const float* bias = (kz == 0) ? bc3 : ((kz == 1) ? bc4 : bc5);
    #pragma unroll
    for (int nf = 0; nf < 4; nf++) {
        int n0 = wn*32 + nf*8 + 2*tq;
        float m0 = -1e30f, m1 = -1e30f;
        #pragma unroll
        for (int mf = 0; mf < 3; mf++) {
            int r0 = mf*16 + g, r1 = r0 + 8;
            if (r0 < T) { m0 = fmaxf(m0, acc[mf][nf][0]); m1 = fmaxf(m1, acc[mf][nf][1]); }
            if (r1 < T) { m0 = fmaxf(m0, acc[mf][nf][2]); m1 = fmaxf(m1, acc[mf][nf][3]); }
        }
        #pragma unroll
        for (int d = 4; d < 32; d <<= 1) {
            m0 = fmaxf(m0, __shfl_xor_sync(0xffffffffu, m0, d));
            m1 = fmaxf(m1, __shfl_xor_sync(0xffffffffu, m1, d));
        }
        if (g == 0 && n0 < 100) {
            float* dst = g_tfeat + (size_t)(s*256 + item)*300 + kz*100;
            dst[n0]     = m0 + bias[s*100 + n0];
            dst[n0 + 1] = m1 + bias[s*100 + n0 + 1];
        }
    }
}

// ---------------- xp = tfeat @ W_ih^T + b_ih + b_hh (gate-split) ------------------
__global__ void xproj_kernel(const float* __restrict__ W_ih,
                             const float* __restrict__ b_ih,
                             const float* __restrict__ b_hh) {
    int s = blockIdx.x, bg = blockIdx.y;
    __shared__ alignas(16) float X[16][300];
    int tid = threadIdx.x;
    for (int i = tid; i < 4800; i += 256) {
        int r = i / 300, e = i % 300;
        X[r][e] = g_tfeat[(size_t)(s*256 + bg*16 + r)*300 + e];
    }
    __syncthreads();
    int g0 = blockIdx.z*256 + tid;
    float acc0[16];
    float bb0 = b_ih[s*512 + g0] + b_hh[s*512 + g0];
    #pragma unroll
    for (int r = 0; r < 16; r++) acc0[r] = bb0;
    const float4* w0 = (const float4*)(W_ih + (size_t)(s*512 + g0) * 300);
    for (int e4 = 0; e4 < 75; e4++) {
        float4 wa = w0[e4];
        #pragma unroll
        for (int r = 0; r < 16; r++) {
            float4 xv = ((const float4*)X[r])[e4];
            acc0[r] += wa.x*xv.x + wa.y*xv.y + wa.z*xv.z + wa.w*xv.w;
        }
    }
    for (int r = 0; r < 16; r++) {
        int bd = bg*16 + r;
        g_xp[(size_t)(s*256 + bd)*512 + g0] = acc0[r];
    }
}

// ---------------- LSTM: one batch per block, grid (10,16) x 256 ----------------
__device__ __forceinline__ float tanh_fast(float x) {
    float r; asm("tanh.approx.f32 %0, %1;" : "=f"(r) : "f"(x)); return r;
}
__device__ __forceinline__ float sigm_fast(float x) {
    return 0.5f * tanh_fast(0.5f * x) + 0.5f;
}

__global__ void lstm_kernel(const float* __restrict__ W_hh) {
    int s = blockIdx.x, b = blockIdx.y;   // one batch per block
    int tid = threadIdx.x;
    int half = tid >> 7, j = tid & 127;
    __shared__ alignas(16) float Hs[128];
    __shared__ float sG[128], sO[128];
    float c = 0.f, hsum = 0.f;
    if (half == 0) Hs[j] = 0.f;
    __syncthreads();
    int rowA = (half == 0) ? j       : 256 + j;   // i or g
    int rowB = (half == 0) ? 128 + j : 384 + j;   // f or o
    const float4* WA = (const float4*)(W_hh + (size_t)(s*512 + rowA) * 128);
    const float4* WB = (const float4*)(W_hh + (size_t)(s*512 + rowB) * 128);
    for (int d = 0; d < 16; d++) {
        size_t base = (size_t)(s*256 + b*16 + d) * 512;
        float gA = g_xp[base + rowA];
        float gB = g_xp[base + rowB];
        #pragma unroll 8
        for (int e4 = 0; e4 < 32; e4++) {
            float4 wa = WA[e4], wb = WB[e4];
            float4 h = ((const float4*)Hs)[e4];
            gA += wa.x*h.x + wa.y*h.y + wa.z*h.z + wa.w*h.w;
            gB += wb.x*h.x + wb.y*h.y + wb.z*h.z + wb.w*h.w;
        }
        if (half == 1) { sG[j] = tanh_fast(gA); sO[j] = sigm_fast(gB); }
        __syncthreads();
        if (half == 0) {
            c = sigm_fast(gB) * c + sigm_fast(gA) * sG[j];
            float hv = sO[j] * tanh_fast(c);
            hsum += hv;
            Hs[j] = hv;
        }
        __syncthreads();
    }
    if (half == 0) {
        g_hn[(s*16 + b)*128 + j]   = Hs[j];
        g_hsum[(s*16 + b)*128 + j] = hsum;
    }
}

// ---------------- per-stock FC ----------------
__global__ void fc_kernel(const float* __restrict__ Wx, const float* __restrict__ bx,
                          const float* __restrict__ Wy, const float* __restrict__ by) {
    int s = blockIdx.x / 16, b = blockIdx.x % 16;
    int j = threadIdx.x;
    __shared__ alignas(16) float V[256];
    __shared__ alignas(16) float Z[128];
    V[j]       = g_hn[(s*16 + b)*128 + j];
    V[128 + j] = g_hsum[(s*16 + b)*128 + j];
    __syncthreads();
    {
        const float4* w = (const float4*)(Wx + (size_t)(s*128 + j) * 256);
        float a = bx[s*128 + j];
        #pragma unroll 8
        for (int e4 = 0; e4 < 64; e4++) {
            float4 wv = w[e4]; float4 vv = ((const float4*)V)[e4];
            a += wv.x*vv.x + wv.y*vv.y + wv.z*vv.z + wv.w*vv.w;
        }
        Z[j] = fmaxf(a, 0.f);
    }
    __syncthreads();
    if (j < 64) {
        const float4* w2 = (const float4*)(Wy + (size_t)(s*64 + j) * 128);
        float a2 = by[s*64 + j];
        #pragma unroll 8
        for (int e4 = 0; e4 < 32; e4++) {
            float4 wv = w2[e4]; float4 zv = ((const float4*)Z)[e4];
            a2 += wv.x*zv.x + wv.y*zv.y + wv.z*zv.z + wv.w*zv.w;
        }
        g_text[b*640 + s*64 + j] = fmaxf(a2, 0.f);
    }
}

// ---------------- head MLP ----------------
__global__ void head_kernel(const float* __restrict__ sfeat, const float* __restrict__ action,
                            const float* __restrict__ W1,  const float* __restrict__ b1,
                            const float* __restrict__ W2,  const float* __restrict__ b2,
                            const float* __restrict__ Wc,  const float* __restrict__ bc,
                            const float* __restrict__ Wca, const float* __restrict__ bca,
                            const float* __restrict__ Wa1, const float* __restrict__ ba1,
                            const float* __restrict__ Wa2, const float* __restrict__ ba2,
                            float* __restrict__ out) {
    int tid = threadIdx.x;
    int b = tid >> 5, u = tid & 31;
    __shared__ float h1[16][24];
    __shared__ float sfm[16][16];
    __shared__ float comb[16][32];
    __shared__ float cam[16][16];
    __shared__ float mid[16][32];
    if (u < 24) {
        float a = b1[u];
        for (int e = 0; e < 100; e++) a += sfeat[b*100 + e] * W1[u*100 + e];
        h1[b][u] = fmaxf(a, 0.f);
    }
    __syncthreads();
    if (u < 16) {
        float a = b2[u];
        for (int e = 0; e < 24; e++) a += h1[b][e] * W2[u*24 + e];
        sfm[b][u] = a;
    }
    __syncthreads();
    {
        float a = bc[u];
        const float* wr = Wc + u*656;
        for (int e = 0; e < 640; e++) a += g_text[b*640 + e] * wr[e];
        for (int e = 0; e < 16;  e++) a += sfm[b][e] * wr[640 + e];
        comb[b][u] = a;
    }
    __syncthreads();
    if (u < 16) {
        float a = bca[u];
        const float* wr = Wca + u*42;
        for (int e = 0; e < 32; e++) a += comb[b][e] * wr[e];
        for (int e = 0; e < 10; e++) a += action[b*10 + e] * wr[32 + e];
        cam[b][u] = a;
    }
    __syncthreads();
    {
        float a = ba1[u];
        for (int e = 0; e < 16; e++) a += cam[b][e] * Wa1[u*16 + e];
        mid[b][u] = fmaxf(a, 0.f);
    }
    __syncthreads();
    if (u == 0) {
        float a = ba2[0];
        for (int e = 0; e < 32; e++) a += mid[b][e] * Wa2[e];
        out[b] = a;
    }
}

// ---------------- launch ----------------
extern "C" void kernel_launch(void* const* d_in, const int* in_sizes, int n_in,
                              void* d_out, int out_size) {
    const float* news  = (const float*)d_in[0];
    const float* sfeat = (const float*)d_in[1];
    const float* act   = (const float*)d_in[2];
    const float* Wc3   = (const float*)d_in[3];
    const float* bc3v  = (const float*)d_in[4];
    const float* Wc4   = (const float*)d_in[5];
    const float* bc4v  = (const float*)d_in[6];
    const float* Wc5   = (const float*)d_in[7];
    const float* bc5v  = (const float*)d_in[8];
    const float* W_ih  = (const float*)d_in[9];
    const float* W_hh  = (const float*)d_in[10];
    const float* b_ih  = (const float*)d_in[11];
    const float* b_hh  = (const float*)d_in[12];
    const float* Wx    = (const float*)d_in[13];
    const float* bxv   = (const float*)d_in[14];
    const float* Wy    = (const float*)d_in[15];
    const float* byv   = (const float*)d_in[16];
    const float* W1    = (const float*)d_in[17];
    const float* b1v   = (const float*)d_in[18];
    const float* W2    = (const float*)d_in[19];
    const float* b2v   = (const float*)d_in[20];
    const float* Wcv   = (const float*)d_in[21];
    const float* bcv   = (const float*)d_in[22];
    const float* Wca   = (const float*)d_in[23];
    const float* bcav  = (const float*)d_in[24];
    const float* Wa1   = (const float*)d_in[25];
    const float* ba1v  = (const float*)d_in[26];
    const float* Wa2   = (const float*)d_in[27];
    const float* ba2v  = (const float*)d_in[28];

    cudaFuncSetAttribute(conv_mma_kernel, cudaFuncAttributeMaxDynamicSharedMemorySize, 204032);

    int prep_items = 10*256*48*40 + 10*3*128*200;
    prep_kernel<<<(prep_items + 255)/256, 256>>>(news, Wc3, Wc4, Wc5);     // launch 1
    conv_mma_kernel<<<dim3(64, 3, 10), 512, 204032>>>(bc3v, bc4v, bc5v);   // launch 2
    xproj_kernel<<<dim3(10, 16, 2), 256>>>(W_ih, b_ih, b_hh);              // launch 3
    lstm_kernel<<<dim3(10, 16), 256>>>(W_hh);                              // launch 4 (ncu slot)
    fc_kernel<<<160, 128>>>(Wx, bxv, Wy, byv);
    head_kernel<<<1, 512>>>(sfeat, act, W1, b1v, W2, b2v, Wcv, bcv,
                            Wca, bcav, Wa1, ba1v, Wa2, ba2v, (float*)d_out);
}

// round 15
// speedup vs baseline: 1.3221x; 1.3221x over previous
#include <cuda_runtime.h>
#include <cuda_fp16.h>
#include <math.h>
#include <stdint.h>

// ================= persistent device scratch =================
__device__ __align__(16) __half g_Bk[10*3*128*1600];      // conv weights fp16
__device__ __align__(16) __half g_Ah[10*256*48*320];      // news fp16
__device__ __align__(16) __half g_Whh[10*512*128];        // LSTM recurrent weights fp16
__device__ float g_tfeat[10*256*300];
__device__ float g_xp[10*256*512];
__device__ float g_hn[10*16*128];
__device__ float g_hsum[10*16*128];
__device__ float g_text[16*640];

// ================= helpers =================
__device__ __forceinline__ uint32_t smem_u32(const void* p) {
    uint32_t a;
    asm("{ .reg .u64 t; cvta.to.shared.u64 t, %1; cvt.u32.u64 %0, t; }" : "=r"(a) : "l"(p));
    return a;
}

#define MMA_F16(c, a, b0, b1) \
    asm volatile("mma.sync.aligned.m16n8k16.row.col.f32.f16.f16.f32 " \
        "{%0,%1,%2,%3}, {%4,%5,%6,%7}, {%8,%9}, {%0,%1,%2,%3};" \
        : "+f"((c)[0]), "+f"((c)[1]), "+f"((c)[2]), "+f"((c)[3]) \
        : "r"((a)[0]), "r"((a)[1]), "r"((a)[2]), "r"((a)[3]), \
          "r"(b0), "r"(b1))

#define LDSM_X4(r0, r1, r2, r3, addr) \
    asm volatile("ldmatrix.sync.aligned.m8n8.x4.shared.b16 {%0,%1,%2,%3}, [%4];" \
        : "=r"(r0), "=r"(r1), "=r"(r2), "=r"(r3) : "r"(addr))

#define CP16(dst, src) \
    asm volatile("cp.async.cg.shared.global [%0], [%1], 16;" :: "r"(dst), "l"(src) : "memory")
#define CP16Z(dst, src, sz) \
    asm volatile("cp.async.cg.shared.global [%0], [%1], 16, %2;" :: "r"(dst), "l"(src), "r"(sz) : "memory")
#define CP_COMMIT() asm volatile("cp.async.commit_group;" ::: "memory")

__device__ __forceinline__ float tanh_fast(float x) {
    float r; asm("tanh.approx.f32 %0, %1;" : "=f"(r) : "f"(x)); return r;
}
__device__ __forceinline__ float sigm_fast(float x) {
    return 0.5f * tanh_fast(0.5f * x) + 0.5f;
}

// ================= merged prep: A + B + Whh(fp16) ==========
__global__ void prep_kernel(const float* __restrict__ news,
                            const float* __restrict__ W3,
                            const float* __restrict__ W4,
                            const float* __restrict__ W5,
                            const float* __restrict__ W_hh) {
    int idx = blockIdx.x * 256 + threadIdx.x;
    const int NA = 10*256*48*40;
    const int NB = 10*3*128*200;
    const int NW = 10*512*128/8;
    if (idx < NA) {
        int e8   = idx % 40;
        int t    = (idx / 40) % 48;
        int item = (idx / (40*48)) % 256;
        int s    = idx / (40*48*256);
        int e0 = e8 * 8;
        int bb = item >> 4, dd = item & 15;
        const float* src = news + ((size_t)((bb*10 + s)*16 + dd)*48 + t)*300 + e0;
        uint32_t pk[4];
        #pragma unroll
        for (int i = 0; i < 4; i++) {
            int e = e0 + i*2;
            float v0 = (e     < 300) ? src[i*2]     : 0.f;
            float v1 = (e + 1 < 300) ? src[i*2 + 1] : 0.f;
            __half2 h = __floats2half2_rn(v0, v1);
            pk[i] = *(uint32_t*)&h;
        }
        *(uint4*)(g_Ah + ((size_t)((s*256 + item)*48 + t))*320 + e0) =
            make_uint4(pk[0], pk[1], pk[2], pk[3]);
    } else if (idx < NA + NB) {
        int jdx = idx - NA;
        int c40 = jdx % 40;
        int kk  = (jdx / 40) % 5;
        int c   = (jdx / 200) % 128;
        int kz  = (jdx / (200*128)) % 3;
        int s   = jdx / (200*128*3);
        int e0 = c40 * 8;
        int K  = 3 + kz;
        uint32_t pk[4];
        #pragma unroll
        for (int i = 0; i < 4; i++) {
            float v0 = 0.f, v1 = 0.f;
            int e = e0 + i*2;
            if (c < 100 && kk < K) {
                if (e < 300) {
                    if (kz == 0)      v0 = W3[((s*100+c)*300+e)*3 + kk];
                    else if (kz == 1) v0 = W4[((s*100+c)*300+e)*4 + kk];
                    else              v0 = W5[((s*100+c)*300+e)*5 + kk];
                }
                if (e + 1 < 300) {
                    if (kz == 0)      v1 = W3[((s*100+c)*300+e+1)*3 + kk];
                    else if (kz == 1) v1 = W4[((s*100+c)*300+e+1)*4 + kk];
                    else              v1 = W5[((s*100+c)*300+e+1)*5 + kk];
                }
            }
            __half2 h = __floats2half2_rn(v0, v1);
            pk[i] = *(uint32_t*)&h;
        }
        *(uint4*)(g_Bk + ((size_t)((s*3 + kz)*128 + c))*1600 + kk*320 + e0) =
            make_uint4(pk[0], pk[1], pk[2], pk[3]);
    } else {
        int kdx = idx - NA - NB;
        if (kdx >= NW) return;
        const float* src = W_hh + (size_t)kdx * 8;
        uint32_t pk[4];
        #pragma unroll
        for (int i = 0; i < 4; i++) {
            __half2 h = __floats2half2_rn(src[i*2], src[i*2+1]);
            pk[i] = *(uint32_t*)&h;
        }
        *(uint4*)(g_Whh + (size_t)kdx * 8) = make_uint4(pk[0], pk[1], pk[2], pk[3]);
    }
}

// ================= fused conv GEMM (proven R11 config) =================
__global__ void __launch_bounds__(512, 1)
conv_mma_kernel(const float* __restrict__ bc3,
                const float* __restrict__ bc4,
                const float* __restrict__ bc5) {
    extern __shared__ char smem[];
    uint32_t sb = smem_u32(smem);
    int tid = threadIdx.x, lane = tid & 31, wid = tid >> 5;
    int wm = wid & 3, wn = wid >> 2;
    int g = lane >> 2, tq = lane & 3;
    int mt = blockIdx.x, kz = blockIdx.y, s = blockIdx.z;
    int it0 = mt * 4;
    int S4 = 4 * (3 + kz);

    float acc[3][4][4];
    #pragma unroll
    for (int mf = 0; mf < 3; mf++)
        #pragma unroll
        for (int nf = 0; nf < 4; nf++)
            #pragma unroll
            for (int i = 0; i < 4; i++) acc[mf][nf][i] = 0.f;

    const __half* Bbase = g_Bk + (size_t)(s*3 + kz) * 128 * 1600;

    for (int c = tid; c < 8528; c += 512) {
        int row = c / 41, ch = c - row*41;
        int item = row / 52, tt = row - item*52;
        uint32_t sz = (tt < 48 && ch < 40) ? 16u : 0u;
        const __half* src = g_Ah +
            ((size_t)((s*256 + it0 + item)*48 + (tt < 48 ? tt : 47)))*320 + (ch < 40 ? ch : 0)*8;
        CP16Z(sb + (uint32_t)(row*656 + ch*16), src, sz);
    }
    CP_COMMIT();

    const __half* bsrc0; const __half* bsrc1; const __half* bsrc2 = 0;
    uint32_t bdst0, bdst1, bdst2 = 0;
    {
        int c = tid;           int n = c/10, ch = c - n*10;
        bsrc0 = Bbase + n*1600 + ch*8;  bdst0 = (uint32_t)(n*176 + ch*16);
        c = tid + 512;         n = c/10; ch = c - n*10;
        bsrc1 = Bbase + n*1600 + ch*8;  bdst1 = (uint32_t)(n*176 + ch*16);
        if (tid < 256) {
            c = tid + 1024;    n = c/10; ch = c - n*10;
            bsrc2 = Bbase + n*1600 + ch*8;  bdst2 = (uint32_t)(n*176 + ch*16);
        }
    }
    auto loadB = [&](int buf, int stoff) {
        uint32_t base = sb + 136448u + (uint32_t)buf * 22528u;
        CP16(base + bdst0, bsrc0 + stoff);
        CP16(base + bdst1, bsrc1 + stoff);
        if (tid < 256) CP16(base + bdst2, bsrc2 + stoff);
    };

    uint32_t a_lm[3], b_lm[2];
    {
        int l15 = lane & 15;
        int hi  = (lane >> 4) & 1;
        #pragma unroll
        for (int mf = 0; mf < 3; mf++)
            a_lm[mf] = (uint32_t)((wm*52 + mf*16 + l15)*656 + hi*16);
        int l7 = lane & 7;
        int k8 = (lane >> 3) & 1;
        #pragma unroll
        for (int p = 0; p < 2; p++)
            b_lm[p] = (uint32_t)((wn*32 + p*16 + l7 + hi*8)*176 + k8*16);
    }

    loadB(0, 0);  CP_COMMIT();
    loadB(1, 80); CP_COMMIT();
    int nk = 0, ne = 160;

    int buf = 0;
    for (int st = 0; st < S4; st++) {
        if (st + 2 < S4) {
            asm volatile("cp.async.wait_group 1;" ::: "memory");
        } else {
            asm volatile("cp.async.wait_group 0;" ::: "memory");
        }
        __syncthreads();
        if (st + 2 < S4) {
            int nb = buf + 2; if (nb >= 3) nb -= 3;
            loadB(nb, nk*320 + ne);
            ne += 80; if (ne == 320) { ne = 0; nk++; }
            CP_COMMIT();
        }

        uint32_t aoff = sb + (uint32_t)(st >> 2)*656u + (uint32_t)(st & 3)*160u;
        uint32_t bbuf = sb + 136448u + (uint32_t)buf * 22528u;
        #pragma unroll
        for (int ks = 0; ks < 5; ks++) {
            uint32_t af[3][4];
            #pragma unroll
            for (int mf = 0; mf < 3; mf++)
                LDSM_X4(af[mf][0], af[mf][1], af[mf][2], af[mf][3],
                        aoff + a_lm[mf] + ks*32);
            uint32_t b0r[4], b1r[4];
            LDSM_X4(b0r[0], b0r[1], b0r[2], b0r[3], bbuf + b_lm[0] + ks*32);
            LDSM_X4(b1r[0], b1r[1], b1r[2], b1r[3], bbuf + b_lm[1] + ks*32);
            #pragma unroll
            for (int mf = 0; mf < 3; mf++) {
                MMA_F16(acc[mf][0], af[mf], b0r[0], b0r[1]);
                MMA_F16(acc[mf][1], af[mf], b0r[2], b0r[3]);
                MMA_F16(acc[mf][2], af[mf], b1r[0], b1r[1]);
                MMA_F16(acc[mf][3], af[mf], b1r[2], b1r[3]);
            }
        }
        buf++; if (buf == 3) buf = 0;
    }

    int item = it0 + wm;
    int T = 46 - kz;
    const float* bias = (kz == 0) ? bc3 : ((kz == 1) ? bc4 : bc5);
    #pragma unroll
    for (int nf = 0; nf < 4; nf++) {
        int n0 = wn*32 + nf*8 + 2*tq;
        float m0 = -1e30f, m1 = -1e30f;
        #pragma unroll
        for (int mf = 0; mf < 3; mf++) {
            int r0 = mf*16 + g, r1 = r0 + 8;
            if (r0 < T) { m0 = fmaxf(m0, acc[mf][nf][0]); m1 = fmaxf(m1, acc[mf][nf][1]); }
            if (r1 < T) { m0 = fmaxf(m0, acc[mf][nf][2]); m1 = fmaxf(m1, acc[mf][nf][3]); }
        }
        #pragma unroll
        for (int d = 4; d < 32; d <<= 1) {
            m0 = fmaxf(m0, __shfl_xor_sync(0xffffffffu, m0, d));
            m1 = fmaxf(m1, __shfl_xor_sync(0xffffffffu, m1, d));
        }
        if (g == 0 && n0 < 100) {
            float* dst = g_tfeat + (size_t)(s*256 + item)*300 + kz*100;
            dst[n0]     = m0 + bias[s*100 + n0];
            dst[n0 + 1] = m1 + bias[s*100 + n0 + 1];
        }
    }
}

// ---------------- xp = tfeat @ W_ih^T + b_ih + b_hh (gate-split) ------------------
__global__ void xproj_kernel(const float* __restrict__ W_ih,
                             const float* __restrict__ b_ih,
                             const float* __restrict__ b_hh) {
    int s = blockIdx.x, bg = blockIdx.y;
    __shared__ alignas(16) float X[16][300];
    int tid = threadIdx.x;
    for (int i = tid; i < 4800; i += 256) {
        int r = i / 300, e = i % 300;
        X[r][e] = g_tfeat[(size_t)(s*256 + bg*16 + r)*300 + e];
    }
    __syncthreads();
    int g0 = blockIdx.z*256 + tid;
    float acc0[16];
    float bb0 = b_ih[s*512 + g0] + b_hh[s*512 + g0];
    #pragma unroll
    for (int r = 0; r < 16; r++) acc0[r] = bb0;
    const float4* w0 = (const float4*)(W_ih + (size_t)(s*512 + g0) * 300);
    for (int e4 = 0; e4 < 75; e4++) {
        float4 wa = w0[e4];
        #pragma unroll
        for (int r = 0; r < 16; r++) {
            float4 xv = ((const float4*)X[r])[e4];
            acc0[r] += wa.x*xv.x + wa.y*xv.y + wa.z*xv.z + wa.w*xv.w;
        }
    }
    for (int r = 0; r < 16; r++) {
        int bd = bg*16 + r;
        g_xp[(size_t)(s*256 + bd)*512 + g0] = acc0[r];
    }
}

// ---------------- LSTM: W_hh fp16 register-resident, grid (10,2) x 512 ----------------
// Thread tid owns gate row tid (64 half2 W regs, loaded once). 8 batches per block.
// h carried in smem as fp16 half2; gates staged in smem (stride 9, conflict-free).
__global__ void __launch_bounds__(512, 1) lstm_kernel() {
    int s = blockIdx.x, bg = blockIdx.y;
    int tid = threadIdx.x;
    __shared__ float G[512*9];            // gate values [row][batch]
    __shared__ uint32_t Hh[8*64];         // h fp16, [batch][64 half2 words]

    // W row -> 64 half2 registers (once)
    uint32_t w[64];
    {
        const uint4* wsrc = (const uint4*)(g_Whh + ((size_t)(s*512 + tid))*128);
        #pragma unroll
        for (int i = 0; i < 16; i++) {
            uint4 v = wsrc[i];
            w[i*4+0] = v.x; w[i*4+1] = v.y; w[i*4+2] = v.z; w[i*4+3] = v.w;
        }
    }
    Hh[tid] = 0u;                          // 512 words = all 8 batches
    float cst[2]  = {0.f, 0.f};
    float hsum[2] = {0.f, 0.f};
    __syncthreads();

    for (int d = 0; d < 16; d++) {
        // ---- compute phase: gate row tid for 8 batches ----
        #pragma unroll
        for (int b = 0; b < 8; b++) {
            int bd = (bg*8 + b)*16 + d;
            float acc = g_xp[((size_t)(s*256 + bd))*512 + tid];
            const uint4* hb4 = (const uint4*)(Hh + b*64);
            #pragma unroll
            for (int c8 = 0; c8 < 8; c8++) {
                uint4 v0 = hb4[c8*2], v1 = hb4[c8*2+1];
                __half2 a = __floats2half2_rn(0.f, 0.f);
                a = __hfma2(*(__half2*)&w[c8*8+0], *(__half2*)&v0.x, a);
                a = __hfma2(*(__half2*)&w[c8*8+1], *(__half2*)&v0.y, a);
                a = __hfma2(*(__half2*)&w[c8*8+2], *(__half2*)&v0.z, a);
                a = __hfma2(*(__half2*)&w[c8*8+3], *(__half2*)&v0.w, a);
                a = __hfma2(*(__half2*)&w[c8*8+4], *(__half2*)&v1.x, a);
                a = __hfma2(*(__half2*)&w[c8*8+5], *(__half2*)&v1.y, a);
                a = __hfma2(*(__half2*)&w[c8*8+6], *(__half2*)&v1.z, a);
                a = __hfma2(*(__half2*)&w[c8*8+7], *(__half2*)&v1.w, a);
                float2 f = __half22float2(a);
                acc += f.x + f.y;
            }
            G[tid*9 + b] = acc;
        }
        __syncthreads();
        // ---- combine phase: tasks (b,u) and (b+4,u) ----
        #pragma unroll
        for (int q = 0; q < 2; q++) {
            int b = (tid >> 7) + q*4;
            int u = tid & 127;
            float gi = G[ u       *9 + b];
            float gf = G[(128 + u)*9 + b];
            float gg = G[(256 + u)*9 + b];
            float go = G[(384 + u)*9 + b];
            cst[q] = sigm_fast(gf)*cst[q] + sigm_fast(gi)*tanh_fast(gg);
            float hv = sigm_fast(go)*tanh_fast(cst[q]);
            hsum[q] += hv;
            ((__half*)Hh)[b*128 + u] = __float2half_rn(hv);
            if (d == 15) {
                int bglob = bg*8 + b;
                g_hn[(s*16 + bglob)*128 + u]   = hv;
                g_hsum[(s*16 + bglob)*128 + u] = hsum[q];
            }
        }
        __syncthreads();
    }
}

// ---------------- per-stock FC ----------------
__global__ void fc_kernel(const float* __restrict__ Wx, const float* __restrict__ bx,
                          const float* __restrict__ Wy, const float* __restrict__ by) {
    int s = blockIdx.x / 16, b = blockIdx.x % 16;
    int j = threadIdx.x;
    __shared__ alignas(16) float V[256];
    __shared__ alignas(16) float Z[128];
    V[j]       = g_hn[(s*16 + b)*128 + j];
    V[128 + j] = g_hsum[(s*16 + b)*128 + j];
    __syncthreads();
    {
        const float4* w = (const float4*)(Wx + (size_t)(s*128 + j) * 256);
        float a = bx[s*128 + j];
        #pragma unroll 8
        for (int e4 = 0; e4 < 64; e4++) {
            float4 wv = w[e4]; float4 vv = ((const float4*)V)[e4];
            a += wv.x*vv.x + wv.y*vv.y + wv.z*vv.z + wv.w*vv.w;
        }
        Z[j] = fmaxf(a, 0.f);
    }
    __syncthreads();
    if (j < 64) {
        const float4* w2 = (const float4*)(Wy + (size_t)(s*64 + j) * 128);
        float a2 = by[s*64 + j];
        #pragma unroll 8
        for (int e4 = 0; e4 < 32; e4++) {
            float4 wv = w2[e4]; float4 zv = ((const float4*)Z)[e4];
            a2 += wv.x*zv.x + wv.y*zv.y + wv.z*zv.z + wv.w*zv.w;
        }
        g_text[b*640 + s*64 + j] = fmaxf(a2, 0.f);
    }
}

// ---------------- head MLP ----------------
__global__ void head_kernel(const float* __restrict__ sfeat, const float* __restrict__ action,
                            const float* __restrict__ W1,  const float* __restrict__ b1,
                            const float* __restrict__ W2,  const float* __restrict__ b2,
                            const float* __restrict__ Wc,  const float* __restrict__ bc,
                            const float* __restrict__ Wca, const float* __restrict__ bca,
                            const float* __restrict__ Wa1, const float* __restrict__ ba1,
                            const float* __restrict__ Wa2, const float* __restrict__ ba2,
                            float* __restrict__ out) {
    int tid = threadIdx.x;
    int b = tid >> 5, u = tid & 31;
    __shared__ float h1[16][24];
    __shared__ float sfm[16][16];
    __shared__ float comb[16][32];
    __shared__ float cam[16][16];
    __shared__ float mid[16][32];
    if (u < 24) {
        float a = b1[u];
        for (int e = 0; e < 100; e++) a += sfeat[b*100 + e] * W1[u*100 + e];
        h1[b][u] = fmaxf(a, 0.f);
    }
    __syncthreads();
    if (u < 16) {
        float a = b2[u];
        for (int e = 0; e < 24; e++) a += h1[b][e] * W2[u*24 + e];
        sfm[b][u] = a;
    }
    __syncthreads();
    {
        float a = bc[u];
        const float* wr = Wc + u*656;
        for (int e = 0; e < 640; e++) a += g_text[b*640 + e] * wr[e];
        for (int e = 0; e < 16;  e++) a += sfm[b][e] * wr[640 + e];
        comb[b][u] = a;
    }
    __syncthreads();
    if (u < 16) {
        float a = bca[u];
        const float* wr = Wca + u*42;
        for (int e = 0; e < 32; e++) a += comb[b][e] * wr[e];
        for (int e = 0; e < 10; e++) a += action[b*10 + e] * wr[32 + e];
        cam[b][u] = a;
    }
    __syncthreads();
    {
        float a = ba1[u];
        for (int e = 0; e < 16; e++) a += cam[b][e] * Wa1[u*16 + e];
        mid[b][u] = fmaxf(a, 0.f);
    }
    __syncthreads();
    if (u == 0) {
        float a = ba2[0];
        for (int e = 0; e < 32; e++) a += mid[b][e] * Wa2[e];
        out[b] = a;
    }
}

// ---------------- launch ----------------
extern "C" void kernel_launch(void* const* d_in, const int* in_sizes, int n_in,
                              void* d_out, int out_size) {
    const float* news  = (const float*)d_in[0];
    const float* sfeat = (const float*)d_in[1];
    const float* act   = (const float*)d_in[2];
    const float* Wc3   = (const float*)d_in[3];
    const float* bc3v  = (const float*)d_in[4];
    const float* Wc4   = (const float*)d_in[5];
    const float* bc4v  = (const float*)d_in[6];
    const float* Wc5   = (const float*)d_in[7];
    const float* bc5v  = (const float*)d_in[8];
    const float* W_ih  = (const float*)d_in[9];
    const float* W_hh  = (const float*)d_in[10];
    const float* b_ih  = (const float*)d_in[11];
    const float* b_hh  = (const float*)d_in[12];
    const float* Wx    = (const float*)d_in[13];
    const float* bxv   = (const float*)d_in[14];
    const float* Wy    = (const float*)d_in[15];
    const float* byv   = (const float*)d_in[16];
    const float* W1    = (const float*)d_in[17];
    const float* b1v   = (const float*)d_in[18];
    const float* W2    = (const float*)d_in[19];
    const float* b2v   = (const float*)d_in[20];
    const float* Wcv   = (const float*)d_in[21];
    const float* bcv   = (const float*)d_in[22];
    const float* Wca   = (const float*)d_in[23];
    const float* bcav  = (const float*)d_in[24];
    const float* Wa1   = (const float*)d_in[25];
    const float* ba1v  = (const float*)d_in[26];
    const float* Wa2   = (const float*)d_in[27];
    const float* ba2v  = (const float*)d_in[28];

    cudaFuncSetAttribute(conv_mma_kernel, cudaFuncAttributeMaxDynamicSharedMemorySize, 204032);

    int prep_items = 10*256*48*40 + 10*3*128*200 + 10*512*128/8;
    prep_kernel<<<(prep_items + 255)/256, 256>>>(news, Wc3, Wc4, Wc5, W_hh);  // 1
    conv_mma_kernel<<<dim3(64, 3, 10), 512, 204032>>>(bc3v, bc4v, bc5v);      // 2
    xproj_kernel<<<dim3(10, 16, 2), 256>>>(W_ih, b_ih, b_hh);                 // 3
    lstm_kernel<<<dim3(10, 2), 512>>>();                                      // 4 (ncu slot)
    fc_kernel<<<160, 128>>>(Wx, bxv, Wy, byv);
    head_kernel<<<1, 512>>>(sfeat, act, W1, b1v, W2, b2v, Wcv, bcv,
                            Wca, bcav, Wa1, ba1v, Wa2, ba2v, (float*)d_out);
}

// round 16
// speedup vs baseline: 1.4863x; 1.1242x over previous
#include <cuda_runtime.h>
#include <cuda_fp16.h>
#include <math.h>
#include <stdint.h>

// ================= persistent device scratch =================
__device__ __align__(16) __half g_Bk[10*3*128*1600];      // conv weights fp16
__device__ __align__(16) __half g_Ah[10*256*48*320];      // news fp16
__device__ __align__(16) __half g_Whh[10*512*128];        // LSTM recurrent weights fp16
__device__ __align__(16) __half g_Wih[10*512*320];        // LSTM input weights fp16 (padded K)
__device__ __align__(16) __half g_tfh[10*256*320];        // TextCNN features fp16 (padded K)
__device__ float g_xp[10*256*512];
__device__ float g_hn[10*16*128];
__device__ float g_hsum[10*16*128];
__device__ float g_text[16*640];

// ================= helpers =================
__device__ __forceinline__ uint32_t smem_u32(const void* p) {
    uint32_t a;
    asm("{ .reg .u64 t; cvta.to.shared.u64 t, %1; cvt.u32.u64 %0, t; }" : "=r"(a) : "l"(p));
    return a;
}

#define MMA_F16(c, a, b0, b1) \
    asm volatile("mma.sync.aligned.m16n8k16.row.col.f32.f16.f16.f32 " \
        "{%0,%1,%2,%3}, {%4,%5,%6,%7}, {%8,%9}, {%0,%1,%2,%3};" \
        : "+f"((c)[0]), "+f"((c)[1]), "+f"((c)[2]), "+f"((c)[3]) \
        : "r"((a)[0]), "r"((a)[1]), "r"((a)[2]), "r"((a)[3]), \
          "r"(b0), "r"(b1))

#define LDSM_X4(r0, r1, r2, r3, addr) \
    asm volatile("ldmatrix.sync.aligned.m8n8.x4.shared.b16 {%0,%1,%2,%3}, [%4];" \
        : "=r"(r0), "=r"(r1), "=r"(r2), "=r"(r3) : "r"(addr))

#define CP16(dst, src) \
    asm volatile("cp.async.cg.shared.global [%0], [%1], 16;" :: "r"(dst), "l"(src) : "memory")
#define CP16Z(dst, src, sz) \
    asm volatile("cp.async.cg.shared.global [%0], [%1], 16, %2;" :: "r"(dst), "l"(src), "r"(sz) : "memory")
#define CP_COMMIT() asm volatile("cp.async.commit_group;" ::: "memory")

__device__ __forceinline__ float tanh_fast(float x) {
    float r; asm("tanh.approx.f32 %0, %1;" : "=f"(r) : "f"(x)); return r;
}
__device__ __forceinline__ float sigm_fast(float x) {
    return 0.5f * tanh_fast(0.5f * x) + 0.5f;
}

// ================= merged prep: A + B + Whh + Wih + tfh-pad-zero ==========
__global__ void prep_kernel(const float* __restrict__ news,
                            const float* __restrict__ W3,
                            const float* __restrict__ W4,
                            const float* __restrict__ W5,
                            const float* __restrict__ W_hh,
                            const float* __restrict__ W_ih) {
    int idx = blockIdx.x * 256 + threadIdx.x;
    const int NA  = 10*256*48*40;       // news chunks
    const int NB  = 10*3*128*200;       // conv weight chunks
    const int NW  = 10*512*128/8;       // Whh chunks
    const int NW2 = 10*512*40;          // Wih chunks (padded K=320)
    const int NT  = 10*256*20;          // tfh pad halves (e 300..319)
    if (idx < NA) {
        int e8   = idx % 40;
        int t    = (idx / 40) % 48;
        int item = (idx / (40*48)) % 256;
        int s    = idx / (40*48*256);
        int e0 = e8 * 8;
        int bb = item >> 4, dd = item & 15;
        const float* src = news + ((size_t)((bb*10 + s)*16 + dd)*48 + t)*300 + e0;
        uint32_t pk[4];
        #pragma unroll
        for (int i = 0; i < 4; i++) {
            int e = e0 + i*2;
            float v0 = (e     < 300) ? src[i*2]     : 0.f;
            float v1 = (e + 1 < 300) ? src[i*2 + 1] : 0.f;
            __half2 h = __floats2half2_rn(v0, v1);
            pk[i] = *(uint32_t*)&h;
        }
        *(uint4*)(g_Ah + ((size_t)((s*256 + item)*48 + t))*320 + e0) =
            make_uint4(pk[0], pk[1], pk[2], pk[3]);
    } else if (idx < NA + NB) {
        int jdx = idx - NA;
        int c40 = jdx % 40;
        int kk  = (jdx / 40) % 5;
        int c   = (jdx / 200) % 128;
        int kz  = (jdx / (200*128)) % 3;
        int s   = jdx / (200*128*3);
        int e0 = c40 * 8;
        int K  = 3 + kz;
        uint32_t pk[4];
        #pragma unroll
        for (int i = 0; i < 4; i++) {
            float v0 = 0.f, v1 = 0.f;
            int e = e0 + i*2;
            if (c < 100 && kk < K) {
                if (e < 300) {
                    if (kz == 0)      v0 = W3[((s*100+c)*300+e)*3 + kk];
                    else if (kz == 1) v0 = W4[((s*100+c)*300+e)*4 + kk];
                    else              v0 = W5[((s*100+c)*300+e)*5 + kk];
                }
                if (e + 1 < 300) {
                    if (kz == 0)      v1 = W3[((s*100+c)*300+e+1)*3 + kk];
                    else if (kz == 1) v1 = W4[((s*100+c)*300+e+1)*4 + kk];
                    else              v1 = W5[((s*100+c)*300+e+1)*5 + kk];
                }
            }
            __half2 h = __floats2half2_rn(v0, v1);
            pk[i] = *(uint32_t*)&h;
        }
        *(uint4*)(g_Bk + ((size_t)((s*3 + kz)*128 + c))*1600 + kk*320 + e0) =
            make_uint4(pk[0], pk[1], pk[2], pk[3]);
    } else if (idx < NA + NB + NW) {
        int kdx = idx - NA - NB;
        const float* src = W_hh + (size_t)kdx * 8;
        uint32_t pk[4];
        #pragma unroll
        for (int i = 0; i < 4; i++) {
            __half2 h = __floats2half2_rn(src[i*2], src[i*2+1]);
            pk[i] = *(uint32_t*)&h;
        }
        *(uint4*)(g_Whh + (size_t)kdx * 8) = make_uint4(pk[0], pk[1], pk[2], pk[3]);
    } else if (idx < NA + NB + NW + NW2) {
        int kdx = idx - NA - NB - NW;
        int c40  = kdx % 40;
        int gate = (kdx / 40) % 512;
        int s    = kdx / (40*512);
        int e0 = c40 * 8;
        const float* src = W_ih + ((size_t)(s*512 + gate))*300;
        uint32_t pk[4];
        #pragma unroll
        for (int i = 0; i < 4; i++) {
            int e = e0 + i*2;
            float v0 = (e     < 300) ? src[e]     : 0.f;
            float v1 = (e + 1 < 300) ? src[e + 1] : 0.f;
            __half2 h = __floats2half2_rn(v0, v1);
            pk[i] = *(uint32_t*)&h;
        }
        *(uint4*)(g_Wih + ((size_t)(s*512 + gate))*320 + e0) =
            make_uint4(pk[0], pk[1], pk[2], pk[3]);
    } else {
        int kdx = idx - NA - NB - NW - NW2;
        if (kdx >= NT) return;
        int e    = 300 + (kdx % 20);
        int item = (kdx / 20) % 256;
        int s    = kdx / (20*256);
        g_tfh[((size_t)(s*256 + item))*320 + e] = __float2half_rn(0.f);
    }
}

// ================= fused conv GEMM (R11 config) -> fp16 tfeat =================
__global__ void __launch_bounds__(512, 1)
conv_mma_kernel(const float* __restrict__ bc3,
                const float* __restrict__ bc4,
                const float* __restrict__ bc5) {
    extern __shared__ char smem[];
    uint32_t sb = smem_u32(smem);
    int tid = threadIdx.x, lane = tid & 31, wid = tid >> 5;
    int wm = wid & 3, wn = wid >> 2;
    int g = lane >> 2, tq = lane & 3;
    int mt = blockIdx.x, kz = blockIdx.y, s = blockIdx.z;
    int it0 = mt * 4;
    int S4 = 4 * (3 + kz);

    float acc[3][4][4];
    #pragma unroll
    for (int mf = 0; mf < 3; mf++)
        #pragma unroll
        for (int nf = 0; nf < 4; nf++)
            #pragma unroll
            for (int i = 0; i < 4; i++) acc[mf][nf][i] = 0.f;

    const __half* Bbase = g_Bk + (size_t)(s*3 + kz) * 128 * 1600;

    for (int c = tid; c < 8528; c += 512) {
        int row = c / 41, ch = c - row*41;
        int item = row / 52, tt = row - item*52;
        uint32_t sz = (tt < 48 && ch < 40) ? 16u : 0u;
        const __half* src = g_Ah +
            ((size_t)((s*256 + it0 + item)*48 + (tt < 48 ? tt : 47)))*320 + (ch < 40 ? ch : 0)*8;
        CP16Z(sb + (uint32_t)(row*656 + ch*16), src, sz);
    }
    CP_COMMIT();

    const __half* bsrc0; const __half* bsrc1; const __half* bsrc2 = 0;
    uint32_t bdst0, bdst1, bdst2 = 0;
    {
        int c = tid;           int n = c/10, ch = c - n*10;
        bsrc0 = Bbase + n*1600 + ch*8;  bdst0 = (uint32_t)(n*176 + ch*16);
        c = tid + 512;         n = c/10; ch = c - n*10;
        bsrc1 = Bbase + n*1600 + ch*8;  bdst1 = (uint32_t)(n*176 + ch*16);
        if (tid < 256) {
            c = tid + 1024;    n = c/10; ch = c - n*10;
            bsrc2 = Bbase + n*1600 + ch*8;  bdst2 = (uint32_t)(n*176 + ch*16);
        }
    }
    auto loadB = [&](int buf, int stoff) {
        uint32_t base = sb + 136448u + (uint32_t)buf * 22528u;
        CP16(base + bdst0, bsrc0 + stoff);
        CP16(base + bdst1, bsrc1 + stoff);
        if (tid < 256) CP16(base + bdst2, bsrc2 + stoff);
    };

    uint32_t a_lm[3], b_lm[2];
    {
        int l15 = lane & 15;
        int hi  = (lane >> 4) & 1;
        #pragma unroll
        for (int mf = 0; mf < 3; mf++)
            a_lm[mf] = (uint32_t)((wm*52 + mf*16 + l15)*656 + hi*16);
        int l7 = lane & 7;
        int k8 = (lane >> 3) & 1;
        #pragma unroll
        for (int p = 0; p < 2; p++)
            b_lm[p] = (uint32_t)((wn*32 + p*16 + l7 + hi*8)*176 + k8*16);
    }

    loadB(0, 0);  CP_COMMIT();
    loadB(1, 80); CP_COMMIT();
    int nk = 0, ne = 160;

    int buf = 0;
    for (int st = 0; st < S4; st++) {
        if (st + 2 < S4) {
            asm volatile("cp.async.wait_group 1;" ::: "memory");
        } else {
            asm volatile("cp.async.wait_group 0;" ::: "memory");
        }
        __syncthreads();
        if (st + 2 < S4) {
            int nb = buf + 2; if (nb >= 3) nb -= 3;
            loadB(nb, nk*320 + ne);
            ne += 80; if (ne == 320) { ne = 0; nk++; }
            CP_COMMIT();
        }

        uint32_t aoff = sb + (uint32_t)(st >> 2)*656u + (uint32_t)(st & 3)*160u;
        uint32_t bbuf = sb + 136448u + (uint32_t)buf * 22528u;
        #pragma unroll
        for (int ks = 0; ks < 5; ks++) {
            uint32_t af[3][4];
            #pragma unroll
            for (int mf = 0; mf < 3; mf++)
                LDSM_X4(af[mf][0], af[mf][1], af[mf][2], af[mf][3],
                        aoff + a_lm[mf] + ks*32);
            uint32_t b0r[4], b1r[4];
            LDSM_X4(b0r[0], b0r[1], b0r[2], b0r[3], bbuf + b_lm[0] + ks*32);
            LDSM_X4(b1r[0], b1r[1], b1r[2], b1r[3], bbuf + b_lm[1] + ks*32);
            #pragma unroll
            for (int mf = 0; mf < 3; mf++) {
                MMA_F16(acc[mf][0], af[mf], b0r[0], b0r[1]);
                MMA_F16(acc[mf][1], af[mf], b0r[2], b0r[3]);
                MMA_F16(acc[mf][2], af[mf], b1r[0], b1r[1]);
                MMA_F16(acc[mf][3], af[mf], b1r[2], b1r[3]);
            }
        }
        buf++; if (buf == 3) buf = 0;
    }

    int item = it0 + wm;
    int T = 46 - kz;
    const float* bias = (kz == 0) ? bc3 : ((kz == 1) ? bc4 : bc5);
    #pragma unroll
    for (int nf = 0; nf < 4; nf++) {
        int n0 = wn*32 + nf*8 + 2*tq;
        float m0 = -1e30f, m1 = -1e30f;
        #pragma unroll
        for (int mf = 0; mf < 3; mf++) {
            int r0 = mf*16 + g, r1 = r0 + 8;
            if (r0 < T) { m0 = fmaxf(m0, acc[mf][nf][0]); m1 = fmaxf(m1, acc[mf][nf][1]); }
            if (r1 < T) { m0 = fmaxf(m0, acc[mf][nf][2]); m1 = fmaxf(m1, acc[mf][nf][3]); }
        }
        #pragma unroll
        for (int d = 4; d < 32; d <<= 1) {
            m0 = fmaxf(m0, __shfl_xor_sync(0xffffffffu, m0, d));
            m1 = fmaxf(m1, __shfl_xor_sync(0xffffffffu, m1, d));
        }
        if (g == 0 && n0 < 100) {
            __half* dst = g_tfh + ((size_t)(s*256 + item))*320 + kz*100;
            dst[n0]     = __float2half_rn(m0 + bias[s*100 + n0]);
            dst[n0 + 1] = __float2half_rn(m1 + bias[s*100 + n0 + 1]);
        }
    }
}

// ================= xproj via fp16 mma: xp = tfh @ Wih^T + b_ih + b_hh ==============
// grid (2, 4, 10): mtile 128 items, ntile 128 gates. 512 threads / 16 warps.
// A resident: 128 rows x 656B = 83968B. B ring 3 x (128 x 176B) at +83968. K=320, 4 stages.
__global__ void __launch_bounds__(512, 1)
xproj_mma_kernel(const float* __restrict__ b_ih, const float* __restrict__ b_hh) {
    extern __shared__ char smem[];
    uint32_t sb = smem_u32(smem);
    int tid = threadIdx.x, lane = tid & 31, wid = tid >> 5;
    int wm = wid & 3, wn = wid >> 2;
    int g = lane >> 2, tq = lane & 3;
    int mt = blockIdx.x, nt = blockIdx.y, s = blockIdx.z;
    int it0 = mt * 128;

    float acc[2][4][4];
    #pragma unroll
    for (int mf = 0; mf < 2; mf++)
        #pragma unroll
        for (int nf = 0; nf < 4; nf++)
            #pragma unroll
            for (int i = 0; i < 4; i++) acc[mf][nf][i] = 0.f;

    const __half* Bbase = g_Wih + ((size_t)(s*512 + nt*128))*320;

    // ---- A resident: 128 rows x 41 chunks = 5248 ----
    for (int c = tid; c < 5248; c += 512) {
        int row = c / 41, ch = c - row*41;
        uint32_t sz = (ch < 40) ? 16u : 0u;
        const __half* src = g_tfh + ((size_t)(s*256 + it0 + row))*320 + (ch < 40 ? ch : 0)*8;
        CP16Z(sb + (uint32_t)(row*656 + ch*16), src, sz);
    }
    CP_COMMIT();

    const __half* bsrc0; const __half* bsrc1; const __half* bsrc2 = 0;
    uint32_t bdst0, bdst1, bdst2 = 0;
    {
        int c = tid;           int n = c/10, ch = c - n*10;
        bsrc0 = Bbase + n*320 + ch*8;  bdst0 = (uint32_t)(n*176 + ch*16);
        c = tid + 512;         n = c/10; ch = c - n*10;
        bsrc1 = Bbase + n*320 + ch*8;  bdst1 = (uint32_t)(n*176 + ch*16);
        if (tid < 256) {
            c = tid + 1024;    n = c/10; ch = c - n*10;
            bsrc2 = Bbase + n*320 + ch*8;  bdst2 = (uint32_t)(n*176 + ch*16);
        }
    }
    auto loadB = [&](int buf, int stoff) {
        uint32_t base = sb + 83968u + (uint32_t)buf * 22528u;
        CP16(base + bdst0, bsrc0 + stoff);
        CP16(base + bdst1, bsrc1 + stoff);
        if (tid < 256) CP16(base + bdst2, bsrc2 + stoff);
    };

    uint32_t a_lm[2], b_lm[2];
    {
        int l15 = lane & 15;
        int hi  = (lane >> 4) & 1;
        #pragma unroll
        for (int mf = 0; mf < 2; mf++)
            a_lm[mf] = (uint32_t)((wm*32 + mf*16 + l15)*656 + hi*16);
        int l7 = lane & 7;
        int k8 = (lane >> 3) & 1;
        #pragma unroll
        for (int p = 0; p < 2; p++)
            b_lm[p] = (uint32_t)((wn*32 + p*16 + l7 + hi*8)*176 + k8*16);
    }

    loadB(0, 0);  CP_COMMIT();
    loadB(1, 80); CP_COMMIT();

    for (int st = 0; st < 4; st++) {
        if (st + 2 < 4) {
            asm volatile("cp.async.wait_group 1;" ::: "memory");
        } else {
            asm volatile("cp.async.wait_group 0;" ::: "memory");
        }
        __syncthreads();
        if (st + 2 < 4) {
            loadB((st + 2) % 3, (st + 2)*80);
            CP_COMMIT();
        }

        uint32_t aoff = sb + (uint32_t)st*160u;
        uint32_t bbuf = sb + 83968u + (uint32_t)(st % 3) * 22528u;
        #pragma unroll
        for (int ks = 0; ks < 5; ks++) {
            uint32_t af[2][4];
            #pragma unroll
            for (int mf = 0; mf < 2; mf++)
                LDSM_X4(af[mf][0], af[mf][1], af[mf][2], af[mf][3],
                        aoff + a_lm[mf] + ks*32);
            uint32_t b0r[4], b1r[4];
            LDSM_X4(b0r[0], b0r[1], b0r[2], b0r[3], bbuf + b_lm[0] + ks*32);
            LDSM_X4(b1r[0], b1r[1], b1r[2], b1r[3], bbuf + b_lm[1] + ks*32);
            #pragma unroll
            for (int mf = 0; mf < 2; mf++) {
                MMA_F16(acc[mf][0], af[mf], b0r[0], b0r[1]);
                MMA_F16(acc[mf][1], af[mf], b0r[2], b0r[3]);
                MMA_F16(acc[mf][2], af[mf], b1r[0], b1r[1]);
                MMA_F16(acc[mf][3], af[mf], b1r[2], b1r[3]);
            }
        }
    }

    // ---- epilogue: add biases, write fp32 xp ----
    #pragma unroll
    for (int nf = 0; nf < 4; nf++) {
        int gate = nt*128 + wn*32 + nf*8 + 2*tq;
        float bb0 = b_ih[s*512 + gate]     + b_hh[s*512 + gate];
        float bb1 = b_ih[s*512 + gate + 1] + b_hh[s*512 + gate + 1];
        #pragma unroll
        for (int mf = 0; mf < 2; mf++) {
            int r0 = it0 + wm*32 + mf*16 + g;
            float* d0 = g_xp + ((size_t)(s*256 + r0))*512 + gate;
            d0[0] = acc[mf][nf][0] + bb0;
            d0[1] = acc[mf][nf][1] + bb1;
            float* d1 = d0 + 8*512;
            d1[0] = acc[mf][nf][2] + bb0;
            d1[1] = acc[mf][nf][3] + bb1;
        }
    }
}

// ---------------- LSTM: W_hh fp16 register-resident, grid (10,4) x 512 ----------------
__global__ void __launch_bounds__(512, 1) lstm_kernel() {
    int s = blockIdx.x, bg = blockIdx.y;
    int tid = threadIdx.x;
    __shared__ float G[512*5];            // gate values [row][batch], stride 5
    __shared__ uint32_t Hh[4*64];         // h fp16, [batch][64 half2 words]

    uint32_t w[64];
    {
        const uint4* wsrc = (const uint4*)(g_Whh + ((size_t)(s*512 + tid))*128);
        #pragma unroll
        for (int i = 0; i < 16; i++) {
            uint4 v = wsrc[i];
            w[i*4+0] = v.x; w[i*4+1] = v.y; w[i*4+2] = v.z; w[i*4+3] = v.w;
        }
    }
    if (tid < 256) Hh[tid] = 0u;
    float cst = 0.f, hsum = 0.f;
    __syncthreads();

    int cb = tid >> 7;            // combine batch 0..3
    int cu = tid & 127;           // combine unit
    for (int d = 0; d < 16; d++) {
        #pragma unroll
        for (int b = 0; b < 4; b++) {
            int bd = (bg*4 + b)*16 + d;
            float acc = g_xp[((size_t)(s*256 + bd))*512 + tid];
            const uint4* hb4 = (const uint4*)(Hh + b*64);
            #pragma unroll
            for (int c8 = 0; c8 < 8; c8++) {
                uint4 v0 = hb4[c8*2], v1 = hb4[c8*2+1];
                __half2 a = __floats2half2_rn(0.f, 0.f);
                a = __hfma2(*(__half2*)&w[c8*8+0], *(__half2*)&v0.x, a);
                a = __hfma2(*(__half2*)&w[c8*8+1], *(__half2*)&v0.y, a);
                a = __hfma2(*(__half2*)&w[c8*8+2], *(__half2*)&v0.z, a);
                a = __hfma2(*(__half2*)&w[c8*8+3], *(__half2*)&v0.w, a);
                a = __hfma2(*(__half2*)&w[c8*8+4], *(__half2*)&v1.x, a);
                a = __hfma2(*(__half2*)&w[c8*8+5], *(__half2*)&v1.y, a);
                a = __hfma2(*(__half2*)&w[c8*8+6], *(__half2*)&v1.z, a);
                a = __hfma2(*(__half2*)&w[c8*8+7], *(__half2*)&v1.w, a);
                float2 f = __half22float2(a);
                acc += f.x + f.y;
            }
            G[tid*5 + b] = acc;
        }
        __syncthreads();
        {
            float gi = G[ cu       *5 + cb];
            float gf = G[(128 + cu)*5 + cb];
            float gg = G[(256 + cu)*5 + cb];
            float go = G[(384 + cu)*5 + cb];
            cst = sigm_fast(gf)*cst + sigm_fast(gi)*tanh_fast(gg);
            float hv = sigm_fast(go)*tanh_fast(cst);
            hsum += hv;
            ((__half*)Hh)[cb*128 + cu] = __float2half_rn(hv);
            if (d == 15) {
                int bglob = bg*4 + cb;
                g_hn[(s*16 + bglob)*128 + cu]   = hv;
                g_hsum[(s*16 + bglob)*128 + cu] = hsum;
            }
        }
        __syncthreads();
    }
}

// ---------------- per-stock FC ----------------
__global__ void fc_kernel(const float* __restrict__ Wx, const float* __restrict__ bx,
                          const float* __restrict__ Wy, const float* __restrict__ by) {
    int s = blockIdx.x / 16, b = blockIdx.x % 16;
    int j = threadIdx.x;
    __shared__ alignas(16) float V[256];
    __shared__ alignas(16) float Z[128];
    V[j]       = g_hn[(s*16 + b)*128 + j];
    V[128 + j] = g_hsum[(s*16 + b)*128 + j];
    __syncthreads();
    {
        const float4* w = (const float4*)(Wx + (size_t)(s*128 + j) * 256);
        float a = bx[s*128 + j];
        #pragma unroll 8
        for (int e4 = 0; e4 < 64; e4++) {
            float4 wv = w[e4]; float4 vv = ((const float4*)V)[e4];
            a += wv.x*vv.x + wv.y*vv.y + wv.z*vv.z + wv.w*vv.w;
        }
        Z[j] = fmaxf(a, 0.f);
    }
    __syncthreads();
    if (j < 64) {
        const float4* w2 = (const float4*)(Wy + (size_t)(s*64 + j) * 128);
        float a2 = by[s*64 + j];
        #pragma unroll 8
        for (int e4 = 0; e4 < 32; e4++) {
            float4 wv = w2[e4]; float4 zv = ((const float4*)Z)[e4];
            a2 += wv.x*zv.x + wv.y*zv.y + wv.z*zv.z + wv.w*zv.w;
        }
        g_text[b*640 + s*64 + j] = fmaxf(a2, 0.f);
    }
}

// ---------------- head MLP ----------------
__global__ void head_kernel(const float* __restrict__ sfeat, const float* __restrict__ action,
                            const float* __restrict__ W1,  const float* __restrict__ b1,
                            const float* __restrict__ W2,  const float* __restrict__ b2,
                            const float* __restrict__ Wc,  const float* __restrict__ bc,
                            const float* __restrict__ Wca, const float* __restrict__ bca,
                            const float* __restrict__ Wa1, const float* __restrict__ ba1,
                            const float* __restrict__ Wa2, const float* __restrict__ ba2,
                            float* __restrict__ out) {
    int tid = threadIdx.x;
    int b = tid >> 5, u = tid & 31;
    __shared__ float h1[16][24];
    __shared__ float sfm[16][16];
    __shared__ float comb[16][32];
    __shared__ float cam[16][16];
    __shared__ float mid[16][32];
    if (u < 24) {
        float a = b1[u];
        for (int e = 0; e < 100; e++) a += sfeat[b*100 + e] * W1[u*100 + e];
        h1[b][u] = fmaxf(a, 0.f);
    }
    __syncthreads();
    if (u < 16) {
        float a = b2[u];
        for (int e = 0; e < 24; e++) a += h1[b][e] * W2[u*24 + e];
        sfm[b][u] = a;
    }
    __syncthreads();
    {
        float a = bc[u];
        const float* wr = Wc + u*656;
        for (int e = 0; e < 640; e++) a += g_text[b*640 + e] * wr[e];
        for (int e = 0; e < 16;  e++) a += sfm[b][e] * wr[640 + e];
        comb[b][u] = a;
    }
    __syncthreads();
    if (u < 16) {
        float a = bca[u];
        const float* wr = Wca + u*42;
        for (int e = 0; e < 32; e++) a += comb[b][e] * wr[e];
        for (int e = 0; e < 10; e++) a += action[b*10 + e] * wr[32 + e];
        cam[b][u] = a;
    }
    __syncthreads();
    {
        float a = ba1[u];
        for (int e = 0; e < 16; e++) a += cam[b][e] * Wa1[u*16 + e];
        mid[b][u] = fmaxf(a, 0.f);
    }
    __syncthreads();
    if (u == 0) {
        float a = ba2[0];
        for (int e = 0; e < 32; e++) a += mid[b][e] * Wa2[e];
        out[b] = a;
    }
}

// ---------------- launch ----------------
extern "C" void kernel_launch(void* const* d_in, const int* in_sizes, int n_in,
                              void* d_out, int out_size) {
    const float* news  = (const float*)d_in[0];
    const float* sfeat = (const float*)d_in[1];
    const float* act   = (const float*)d_in[2];
    const float* Wc3   = (const float*)d_in[3];
    const float* bc3v  = (const float*)d_in[4];
    const float* Wc4   = (const float*)d_in[5];
    const float* bc4v  = (const float*)d_in[6];
    const float* Wc5   = (const float*)d_in[7];
    const float* bc5v  = (const float*)d_in[8];
    const float* W_ih  = (const float*)d_in[9];
    const float* W_hh  = (const float*)d_in[10];
    const float* b_ih  = (const float*)d_in[11];
    const float* b_hh  = (const float*)d_in[12];
    const float* Wx    = (const float*)d_in[13];
    const float* bxv   = (const float*)d_in[14];
    const float* Wy    = (const float*)d_in[15];
    const float* byv   = (const float*)d_in[16];
    const float* W1    = (const float*)d_in[17];
    const float* b1v   = (const float*)d_in[18];
    const float* W2    = (const float*)d_in[19];
    const float* b2v   = (const float*)d_in[20];
    const float* Wcv   = (const float*)d_in[21];
    const float* bcv   = (const float*)d_in[22];
    const float* Wca   = (const float*)d_in[23];
    const float* bcav  = (const float*)d_in[24];
    const float* Wa1   = (const float*)d_in[25];
    const float* ba1v  = (const float*)d_in[26];
    const float* Wa2   = (const float*)d_in[27];
    const float* ba2v  = (const float*)d_in[28];

    cudaFuncSetAttribute(conv_mma_kernel, cudaFuncAttributeMaxDynamicSharedMemorySize, 204032);
    cudaFuncSetAttribute(xproj_mma_kernel, cudaFuncAttributeMaxDynamicSharedMemorySize, 151552);

    int prep_items = 10*256*48*40 + 10*3*128*200 + 10*512*128/8 + 10*512*40 + 10*256*20;
    prep_kernel<<<(prep_items + 255)/256, 256>>>(news, Wc3, Wc4, Wc5, W_hh, W_ih); // 1
    conv_mma_kernel<<<dim3(64, 3, 10), 512, 204032>>>(bc3v, bc4v, bc5v);           // 2
    xproj_mma_kernel<<<dim3(2, 4, 10), 512, 151552>>>(b_ih, b_hh);                 // 3
    lstm_kernel<<<dim3(10, 4), 512>>>();                                           // 4 (ncu slot)
    fc_kernel<<<160, 128>>>(Wx, bxv, Wy, byv);
    head_kernel<<<1, 512>>>(sfeat, act, W1, b1v, W2, b2v, Wcv, bcv,
                            Wca, bcav, Wa1, ba1v, Wa2, ba2v, (float*)d_out);
}